// round 2
// baseline (speedup 1.0000x reference)
#include <cuda_runtime.h>

#define T_STEPS 4096
#define BATCH   64
#define NSEQ    192   // 3 splits * 64 batch
#define FDIM    64

// Scratch (device globals are the allowed scratch mechanism)
__device__ float g_Z[(size_t)NSEQ * T_STEPS * 12];  // 37.7 MB, pre-scaled preactivations, [seq][t][u][gate]
__device__ float g_H[(size_t)NSEQ * T_STEPS * 3];   // 9.4 MB, hidden states

__device__ __forceinline__ float tanh_fast(float x) {
    float r;
    asm("tanh.approx.f32 %0, %1;" : "=f"(r) : "f"(x));
    return r;
}

// ---------------------------------------------------------------------------
// Kernel 1: Z'[seq][t][u][g] = 0.5 * ( x[b,t, s*64 + :] @ W[:, g*3+u] + b[g*3+u] )
// One thread per (b,t,s) row; row data is contiguous 256B at gid*64 floats.
// ---------------------------------------------------------------------------
__global__ void k1_gemm(const float* __restrict__ x,
                        const float* __restrict__ W,
                        const float* __restrict__ bias) {
    __shared__ float Ws[FDIM * 12];
    __shared__ float bs[12];
    int tid = threadIdx.x;
    for (int i = tid; i < FDIM * 12; i += blockDim.x) Ws[i] = W[i];
    if (tid < 12) bs[tid] = bias[tid];
    __syncthreads();

    int gid = blockIdx.x * blockDim.x + tid;      // gid = (b*T + t)*3 + s
    int s   = gid % 3;
    int rem = gid / 3;
    int t   = rem % T_STEPS;
    int bb  = rem / T_STEPS;

    const float4* xp = (const float4*)(x + (size_t)gid * FDIM);

    float acc[12];
#pragma unroll
    for (int j = 0; j < 12; j++) acc[j] = bs[j];

#pragma unroll
    for (int k = 0; k < FDIM / 4; k++) {
        float4 xv = xp[k];
#pragma unroll
        for (int j = 0; j < 12; j++) {
            acc[j] = fmaf(xv.x, Ws[(4 * k + 0) * 12 + j], acc[j]);
            acc[j] = fmaf(xv.y, Ws[(4 * k + 1) * 12 + j], acc[j]);
            acc[j] = fmaf(xv.z, Ws[(4 * k + 2) * 12 + j], acc[j]);
            acc[j] = fmaf(xv.w, Ws[(4 * k + 3) * 12 + j], acc[j]);
        }
    }

    int seq = s * BATCH + bb;
    float4* zp = (float4*)(g_Z + ((size_t)seq * T_STEPS + t) * 12);
#pragma unroll
    for (int u = 0; u < 3; u++) {
        float4 v;
        v.x = 0.5f * acc[0 * 3 + u];   // gate i
        v.y = 0.5f * acc[1 * 3 + u];   // gate f
        v.z = 0.5f * acc[2 * 3 + u];   // gate g
        v.w = 0.5f * acc[3 * 3 + u];   // gate o
        zp[u] = v;
    }
}

// ---------------------------------------------------------------------------
// Kernel 2: recurrence. 3 lanes per sequence (lane = unit), 10 seq per warp,
// one warp per block. State d = c/2 so sigmoid(x)=0.5+0.5*tanh(x/2) folds to
// bare tanh on pre-scaled preactivations.
// ---------------------------------------------------------------------------
__global__ void k2_lstm(const float* __restrict__ U) {
    int lane = threadIdx.x;
    int grp  = lane / 3;
    int u    = lane - grp * 3;
    int seq  = blockIdx.x * 10 + grp;
    bool active = (lane < 30) && (seq < NSEQ);
    int seqc = active ? seq : 0;

    int ua = u + 1; if (ua >= 3) ua -= 3;
    int ub = u + 2; if (ub >= 3) ub -= 3;
    int la = grp * 3 + ua;
    int lb = grp * 3 + ub;

    // Scaled recurrent weights: row k of U, column g*3+u, times 0.5
    float Uo[4], Uaa[4], Ubb[4];
#pragma unroll
    for (int g = 0; g < 4; g++) {
        Uo[g]  = 0.5f * U[u  * 12 + g * 3 + u];
        Uaa[g] = 0.5f * U[ua * 12 + g * 3 + u];
        Ubb[g] = 0.5f * U[ub * 12 + g * 3 + u];
    }

    const float4* zp = (const float4*)(g_Z + (size_t)seqc * T_STEPS * 12) + u;  // stride 3 float4 per t
    float*        hp = g_H + (size_t)seqc * T_STEPS * 3 + u;

    const int PD = 8;  // prefetch depth (~8*90 cyc covers DRAM latency)
    float4 ring[PD];
#pragma unroll
    for (int p = 0; p < PD; p++) ring[p] = zp[(size_t)p * 3];

    float h = 0.0f, d = 0.0f;

    for (int t0 = 0; t0 < T_STEPS; t0 += PD) {
#pragma unroll
        for (int q = 0; q < PD; q++) {
            int t = t0 + q;
            float4 zv = ring[q];
            int tp = t + PD; if (tp > T_STEPS - 1) tp = T_STEPS - 1;
            ring[q] = zp[(size_t)tp * 3];

            float ha = __shfl_sync(0xffffffffu, h, la);
            float hb = __shfl_sync(0xffffffffu, h, lb);

            // gate preactivations (already scaled by 0.5)
            float p0 = fmaf(h, Uo[0], zv.x);
            float p1 = fmaf(h, Uo[1], zv.y);
            float p2 = fmaf(h, Uo[2], zv.z);
            float p3 = fmaf(h, Uo[3], zv.w);
            float pre0 = fmaf(ha, Uaa[0], p0) + hb * Ubb[0];
            float pre1 = fmaf(ha, Uaa[1], p1) + hb * Ubb[1];
            float pre2 = fmaf(ha, Uaa[2], p2) + hb * Ubb[2];
            float pre3 = fmaf(ha, Uaa[3], p3) + hb * Ubb[3];

            float ti = tanh_fast(pre0);
            float tf = tanh_fast(pre1);
            float tg = tanh_fast(pre2);
            float to = tanh_fast(pre3);

            float ih = fmaf(ti, 0.25f, 0.25f);  // sigma(zi)/2
            float gf = fmaf(tg, 0.50f, 0.50f);  // sigma(zg)
            float ff = fmaf(tf, 0.50f, 0.50f);  // sigma(zf)
            float oh = fmaf(to, 0.25f, 0.25f);  // sigma(zo)/2

            d = fmaf(ff, d, ih * gf);           // d = c_new/2
            float tc = tanh_fast(d);            // tanh(c_new/2)
            h = fmaf(oh, tc, oh);               // sigma(zo)*sigma(c_new)

            if (active) hp[(size_t)t * 3] = h;
        }
    }
}

// ---------------------------------------------------------------------------
// Kernel 3: out[b,t,:] = sigmoid( concat_s h[s,b,t,:] @ Wd + bd )
// One thread per (b,t); float4 store.
// ---------------------------------------------------------------------------
__global__ void k3_dense(const float* __restrict__ Wd,
                         const float* __restrict__ bd,
                         float* __restrict__ out) {
    __shared__ float Wds[36];
    __shared__ float bds[4];
    int tid = threadIdx.x;
    if (tid < 36) Wds[tid] = Wd[tid];
    if (tid < 4)  bds[tid] = bd[tid];
    __syncthreads();

    int gid = blockIdx.x * blockDim.x + tid;  // gid = b*T + t
    int t  = gid % T_STEPS;
    int bb = gid / T_STEPS;

    float a0 = bds[0], a1 = bds[1], a2 = bds[2], a3 = bds[3];
#pragma unroll
    for (int s = 0; s < 3; s++) {
        const float* hpp = g_H + ((size_t)(s * BATCH + bb) * T_STEPS + t) * 3;
#pragma unroll
        for (int uu = 0; uu < 3; uu++) {
            float hv = hpp[uu];
            int m = s * 3 + uu;
            a0 = fmaf(hv, Wds[m * 4 + 0], a0);
            a1 = fmaf(hv, Wds[m * 4 + 1], a1);
            a2 = fmaf(hv, Wds[m * 4 + 2], a2);
            a3 = fmaf(hv, Wds[m * 4 + 3], a3);
        }
    }
    float4 r;
    r.x = 1.0f / (1.0f + __expf(-a0));
    r.y = 1.0f / (1.0f + __expf(-a1));
    r.z = 1.0f / (1.0f + __expf(-a2));
    r.w = 1.0f / (1.0f + __expf(-a3));
    ((float4*)out)[gid] = r;
}

extern "C" void kernel_launch(void* const* d_in, const int* in_sizes, int n_in,
                              void* d_out, int out_size) {
    const float* x    = (const float*)d_in[0];
    const float* W    = (const float*)d_in[1];
    const float* U    = (const float*)d_in[2];
    const float* bias = (const float*)d_in[3];
    const float* Wd   = (const float*)d_in[4];
    const float* bd   = (const float*)d_in[5];
    float* out = (float*)d_out;

    // 786432 rows, 1 thread each
    k1_gemm<<<3072, 256>>>(x, W, bias);
    // 192 sequences, 10 per warp, 1 warp per block
    k2_lstm<<<20, 32>>>(U);
    // 262144 (b,t) pairs
    k3_dense<<<1024, 256>>>(Wd, bd, out);

    (void)in_sizes; (void)n_in; (void)out_size;
}